// round 10
// baseline (speedup 1.0000x reference)
#include <cuda_runtime.h>
#include <cuda_bf16.h>
#include <math.h>
#include <stdint.h>

// Problem constants (fixed by setup_inputs)
#define NB      8
#define NA      16
#define NL      80
#define DIM     128
#define NH      6
#define HD      768
#define N_AGT   128
#define N_NODE  768
#define SPS     96
#define NQKV    2304          // 3 * HD
#define LN_EPS  1e-5f

#define NCTA    128
#define NTHR    512

// Scratch (device globals: no allocations allowed)
__device__ float g_QKV[N_NODE * NQKV];        // cols: [Q | K | V(relu)]
__device__ float g_part[NH * N_AGT * DIM];    // per-head partials of attO@Wout1
__device__ unsigned g_gen = 0;                 // grid barrier generation
__device__ unsigned g_cnt = 0;                 // grid barrier counter

// ---------------------------------------------------------------------------
// Helpers
// ---------------------------------------------------------------------------
__device__ __forceinline__ uint32_t smem_u32(const void* p) {
    uint32_t a;
    asm("{ .reg .u64 t; cvta.to.shared.u64 t, %1; cvt.u32.u64 %0, t; }"
        : "=r"(a) : "l"(p));
    return a;
}
__device__ __forceinline__ void ldsm4(uint32_t* r, uint32_t a) {
    asm volatile("ldmatrix.sync.aligned.m8n8.x4.shared.b16 {%0,%1,%2,%3}, [%4];"
                 : "=r"(r[0]), "=r"(r[1]), "=r"(r[2]), "=r"(r[3]) : "r"(a));
}
__device__ __forceinline__ void ldsm2t(uint32_t* r, uint32_t a) {
    asm volatile("ldmatrix.sync.aligned.m8n8.x2.trans.shared.b16 {%0,%1}, [%2];"
                 : "=r"(r[0]), "=r"(r[1]) : "r"(a));
}
__device__ __forceinline__ void mma_bf16(float* d, const uint32_t* a,
                                         const uint32_t* b) {
    asm volatile(
        "mma.sync.aligned.m16n8k16.row.col.f32.bf16.bf16.f32 "
        "{%0,%1,%2,%3}, {%4,%5,%6,%7}, {%8,%9}, {%0,%1,%2,%3};"
        : "+f"(d[0]), "+f"(d[1]), "+f"(d[2]), "+f"(d[3])
        : "r"(a[0]), "r"(a[1]), "r"(a[2]), "r"(a[3]), "r"(b[0]), "r"(b[1]));
}
__device__ __forceinline__ void split2(float x, float y,
                                       uint32_t& hi, uint32_t& lo) {
    __nv_bfloat16 hx = __float2bfloat16_rn(x);
    __nv_bfloat16 hy = __float2bfloat16_rn(y);
    __nv_bfloat16 lx = __float2bfloat16_rn(x - __bfloat162float(hx));
    __nv_bfloat16 ly = __float2bfloat16_rn(y - __bfloat162float(hy));
    __nv_bfloat162 h = __halves2bfloat162(hx, hy);
    __nv_bfloat162 l = __halves2bfloat162(lx, ly);
    hi = *(uint32_t*)&h;
    lo = *(uint32_t*)&l;
}

// Grid-wide barrier: counter + monotonic generation (safe across graph replays)
__device__ __forceinline__ void grid_barrier() {
    __threadfence();
    __syncthreads();
    if (threadIdx.x == 0) {
        volatile unsigned* vg = &g_gen;
        unsigned my = *vg;
        if (atomicAdd(&g_cnt, 1u) == NCTA - 1u) {
            g_cnt = 0u;
            __threadfence();
            *vg = my + 1u;
        } else {
            while (*vg == my) { }
        }
    }
    __syncthreads();
    __threadfence();
}

// ---------------------------------------------------------------------------
// Fused single kernel: Phase A (QKV mma) -> barrier -> Phase B (attention +
// per-head Wout1 partial) -> barrier -> Phase C (tail MLP + LN).
// Grid 128 CTAs x 512 threads: all CTAs resident (<=148 SMs), 16 warps/SM.
// ---------------------------------------------------------------------------
#define ASTR   136                       // A row stride (bf16)
#define BSTR   72                        // B row stride (bf16)
#define TA     (128 * ASTR * 2)          // 34816 B
#define TBB    (128 * BSTR * 2)          // 18432 B
#define KP     132
#define SP     100
#define FUSED_SMEM ((SPS*KP + SPS*DIM + NA*KP + NA*SP) * 4)   // 114688 B (max)

__global__ __launch_bounds__(NTHR)
void fused_kernel(const float* __restrict__ agents,
                  const float* __restrict__ lanes,
                  const float* __restrict__ Wq,
                  const float* __restrict__ Wk,
                  const float* __restrict__ Wv,
                  const float* __restrict__ Wout1,
                  const float* __restrict__ Wout2,
                  const float* __restrict__ W1,
                  const float* __restrict__ lng,
                  const float* __restrict__ lnb,
                  const float* __restrict__ W2,
                  float* __restrict__ out)
{
    extern __shared__ float sm[];
    const uint32_t sb = smem_u32(sm);
    const int tid = threadIdx.x, wid = tid >> 5, lane = tid & 31;
    const int cta = blockIdx.x;

    // ===================== Phase A: QKV bf16x3 MMA =====================
    {
        char* Ahi = (char*)sm;
        char* Alo = (char*)sm + TA;
        char* Bhi = (char*)sm + 2 * TA;
        char* Blo = (char*)sm + 2 * TA + TBB;

        for (int t = cta; t < 156; t += NCTA) {
            __syncthreads();
            int row0, col0;
            if (t < 144) { row0 = (t % 6) * 128; col0 = 768 + (t / 6) * 64; }
            else         { row0 = 0;              col0 = (t - 144) * 64;    }
            const float* __restrict__ W;
            int jl0;
            if (col0 < HD)          { W = Wq; jl0 = col0; }
            else if (col0 < 2 * HD) { W = Wk; jl0 = col0 - HD; }
            else                    { W = Wv; jl0 = col0 - 2 * HD; }

            // Fill A (128 x 128) with fp32->bf16 hi/lo conversion
            #pragma unroll
            for (int i = 0; i < 8; ++i) {
                int lin = tid + i * NTHR;            // 0..4095
                int q4 = (lin & 31) * 4;
                int rk = lin >> 5;
                int grow = row0 + rk;
                const float* asrc = (grow < N_AGT) ? agents + grow * DIM
                                                   : lanes + (grow - N_AGT) * DIM;
                float4 av = *(const float4*)(asrc + q4);
                uint32_t h0, l0, h1, l1;
                split2(av.x, av.y, h0, l0);
                split2(av.z, av.w, h1, l1);
                *(uint2*)(Ahi + rk * (ASTR * 2) + q4 * 2) = make_uint2(h0, h1);
                *(uint2*)(Alo + rk * (ASTR * 2) + q4 * 2) = make_uint2(l0, l1);
            }
            // Fill B (128 k x 64 n)
            #pragma unroll
            for (int i = 0; i < 4; ++i) {
                int lin = tid + i * NTHR;            // 0..2047
                int n4 = (lin & 15) * 4;
                int k = lin >> 4;
                float4 bv = *(const float4*)(W + k * HD + jl0 + n4);
                uint32_t h0, l0, h1, l1;
                split2(bv.x, bv.y, h0, l0);
                split2(bv.z, bv.w, h1, l1);
                *(uint2*)(Bhi + k * (BSTR * 2) + n4 * 2) = make_uint2(h0, h1);
                *(uint2*)(Blo + k * (BSTR * 2) + n4 * 2) = make_uint2(l0, l1);
            }
            __syncthreads();

            // 16 warps: 8m x 2n, warp tile 16x32
            const int wm = wid >> 1, wn = wid & 1;
            const int m0 = wm * 16, n0 = wn * 32;
            float acc[4][4] = {};

            const uint32_t a_off = (uint32_t)((m0 + (lane & 15)) * ASTR +
                                              (lane >> 4) * 8) * 2;
            const uint32_t b_off = (uint32_t)((lane & 15) * BSTR + n0) * 2;
            const uint32_t sA_hi = sb + a_off;
            const uint32_t sA_lo = sb + TA + a_off;
            const uint32_t sB_hi = sb + 2 * TA + b_off;
            const uint32_t sB_lo = sb + 2 * TA + TBB + b_off;

            #pragma unroll 2
            for (int ks = 0; ks < 8; ++ks) {
                const uint32_t kbA = (uint32_t)(ks * 32);
                const uint32_t kbB = (uint32_t)(ks * 16 * BSTR * 2);
                uint32_t ah[4], al[4], bh[4][2], bl[4][2];
                ldsm4(ah, sA_hi + kbA);
                ldsm4(al, sA_lo + kbA);
                #pragma unroll
                for (int nt = 0; nt < 4; ++nt) {
                    ldsm2t(bh[nt], sB_hi + kbB + nt * 16);
                    ldsm2t(bl[nt], sB_lo + kbB + nt * 16);
                }
                #pragma unroll
                for (int nt = 0; nt < 4; ++nt) {
                    mma_bf16(acc[nt], ah, bh[nt]);
                    mma_bf16(acc[nt], ah, bl[nt]);
                    mma_bf16(acc[nt], al, bh[nt]);
                }
            }

            const bool dorelu = (col0 >= 2 * HD);
            const int rbase = row0 + m0 + (lane >> 2);
            const int cbase = col0 + n0 + (lane & 3) * 2;
            #pragma unroll
            for (int nt = 0; nt < 4; ++nt) {
                float2 v01 = make_float2(acc[nt][0], acc[nt][1]);
                float2 v23 = make_float2(acc[nt][2], acc[nt][3]);
                if (dorelu) {
                    v01.x = fmaxf(v01.x, 0.f); v01.y = fmaxf(v01.y, 0.f);
                    v23.x = fmaxf(v23.x, 0.f); v23.y = fmaxf(v23.y, 0.f);
                }
                int c = cbase + nt * 8;
                *(float2*)(g_QKV + (size_t)rbase * NQKV + c) = v01;
                *(float2*)(g_QKV + (size_t)(rbase + 8) * NQKV + c) = v23;
            }
        }
    }

    grid_barrier();

    // ===================== Phase B: attention (CTAs 0..47) =====================
    if (cta < NB * NH) {
        const int b = cta / NH;
        const int h = cta % NH;
        float* Kt = sm;                      // [96][KP]
        float* Vt = Kt + SPS * KP;           // [96][128]
        float* Qs = Vt + SPS * DIM;          // [16][KP] -> later Ot[16][128]
        float* S  = Qs + NA * KP;            // [16][SP]

        #pragma unroll
        for (int i = 0; i < 6; ++i) {
            int lin = tid + i * NTHR;        // 0..3071
            int j = lin >> 5, f = lin & 31;
            int g = (j < NA) ? (b * NA + j) : (N_AGT + b * NL + (j - NA));
            const float* base = g_QKV + (size_t)g * NQKV + h * DIM + f * 4;
            *(float4*)(Kt + j * KP + f * 4) = *(const float4*)(base + HD);
            *(float4*)(Vt + j * DIM + f * 4) = *(const float4*)(base + 2 * HD);
        }
        {
            int r = tid >> 5, f = tid & 31;  // 512 = 16 rows x 32 float4
            *(float4*)(Qs + r * KP + f * 4) =
                *(const float4*)(g_QKV + (size_t)(b * NA + r) * NQKV + h * DIM + f * 4);
        }
        __syncthreads();

        // Scores: 384 threads, thread = (4 rows, 1 col)
        const float scale = 0.08838834764831845f;
        if (tid < 384) {
            const int ti = tid / SPS;        // 0..3
            const int tj = tid % SPS;        // col j
            const int ib = ti * 4;
            float acc[4] = {};
            #pragma unroll 4
            for (int k = 0; k < DIM; k += 4) {
                float4 kv = *(const float4*)(Kt + tj * KP + k);
                #pragma unroll
                for (int r = 0; r < 4; ++r) {
                    float4 q = *(const float4*)(Qs + (ib + r) * KP + k);
                    acc[r] += q.x * kv.x + q.y * kv.y + q.z * kv.z + q.w * kv.w;
                }
            }
            #pragma unroll
            for (int r = 0; r < 4; ++r)
                S[(ib + r) * SP + tj] = acc[r] * scale;
        }
        __syncthreads();

        // Softmax: warp w -> row w
        {
            const int i = wid;
            float v0 = S[i * SP + lane];
            float v1 = S[i * SP + lane + 32];
            float v2 = S[i * SP + lane + 64];
            float m = fmaxf(fmaxf(v0, v1), v2);
            #pragma unroll
            for (int off = 16; off > 0; off >>= 1)
                m = fmaxf(m, __shfl_xor_sync(0xffffffffu, m, off));
            float e0 = __expf(v0 - m), e1 = __expf(v1 - m), e2 = __expf(v2 - m);
            float s = e0 + e1 + e2;
            #pragma unroll
            for (int off = 16; off > 0; off >>= 1)
                s += __shfl_xor_sync(0xffffffffu, s, off);
            float rinv = 1.0f / s;
            S[i * SP + lane]      = e0 * rinv;
            S[i * SP + lane + 32] = e1 * rinv;
            S[i * SP + lane + 64] = e2 * rinv;
        }
        __syncthreads();

        // PV: warp = row, lane = 4 cols
        float* Ot = Qs;
        {
            const int i = wid;
            const int d = lane * 4;
            float4 a0 = make_float4(0.f, 0.f, 0.f, 0.f);
            #pragma unroll 4
            for (int k = 0; k < SPS; ++k) {
                float p = S[i * SP + k];
                float4 v = *(const float4*)(Vt + k * DIM + d);
                a0.x += p * v.x; a0.y += p * v.y; a0.z += p * v.z; a0.w += p * v.w;
            }
            *(float4*)(Ot + i * DIM + d) = a0;
        }
        __syncthreads();

        // Partial P1 = Ot(16x128) @ Wout1[h*128 .. +128, :]  (4-way k split)
        {
            const int c = tid & 127;
            const int ks = tid >> 7;         // 0..3
            float acc[NA] = {};
            const float* Wb = Wout1 + (size_t)(h * DIM + ks * 32) * DIM + c;
            #pragma unroll 8
            for (int kk = 0; kk < 32; ++kk) {
                float w = Wb[kk * DIM];
                const float* o = Ot + ks * 32 + kk;
                #pragma unroll
                for (int r = 0; r < NA; ++r)
                    acc[r] += o[r * DIM] * w;
            }
            float* red = Kt;                 // [3][16][128] fits in Kt region
            if (ks > 0) {
                #pragma unroll
                for (int r = 0; r < NA; ++r)
                    red[(ks - 1) * (NA * DIM) + r * DIM + c] = acc[r];
            }
            __syncthreads();
            if (ks == 0) {
                float* dst = g_part + (size_t)h * N_AGT * DIM +
                             (size_t)(b * NA) * DIM + c;
                #pragma unroll
                for (int r = 0; r < NA; ++r)
                    dst[r * DIM] = acc[r] + red[r * DIM + c]
                                          + red[NA * DIM + r * DIM + c]
                                          + red[2 * NA * DIM + r * DIM + c];
            }
        }
    }

    grid_barrier();

    // ===================== Phase C: tail (1 row per CTA) =====================
    {
        const int r = cta;
        const int c = tid & 127;
        const int ks = tid >> 7;             // 0..3

        float* s_ar = sm;                    // [128]
        float* s_t1 = sm + 128;              // [128]
        float* s_h  = sm + 256;              // [128]
        float* s_p  = sm + 384;              // [4][128]
        float* s_red = sm + 896;             // [8]

        float wv2[32], wv1[32];
        {
            const float* w2b = Wout2 + (size_t)(ks * 32) * DIM + c;
            const float* w1b = W1 + (size_t)(ks * 32) * DIM + c;
            #pragma unroll
            for (int k = 0; k < 32; ++k) {
                wv2[k] = w2b[k * DIM];
                wv1[k] = w1b[k * DIM];
            }
        }
        float tp = 0.0f;
        if (ks < 3) {
            const float* gp = g_part + (size_t)(2 * ks) * N_AGT * DIM +
                              (size_t)r * DIM + c;
            tp = gp[0] + gp[N_AGT * DIM];
        }
        const float ar = agents[r * DIM + c];
        const float g_c = lng[c], b_c = lnb[c];

        s_p[ks * DIM + c] = tp;
        __syncthreads();
        if (ks == 0) {
            s_t1[c] = fmaxf(s_p[c] + s_p[DIM + c] + s_p[2 * DIM + c], 0.0f);
            s_ar[c] = ar;
        }
        __syncthreads();

        float pp = 0.0f;
        {
            const float* t1b = s_t1 + ks * 32;
            const float* arb = s_ar + ks * 32;
            #pragma unroll
            for (int k = 0; k < 32; ++k)
                pp += t1b[k] * wv2[k] + arb[k] * wv1[k];
        }
        s_p[ks * DIM + c] = pp;

        float wv3[32];
        {
            const float* w3b = W2 + (size_t)(ks * 32) * DIM + c;
            #pragma unroll
            for (int k = 0; k < 32; ++k) wv3[k] = w3b[k * DIM];
        }
        __syncthreads();

        const float pre = s_p[c] + s_p[DIM + c] + s_p[2 * DIM + c] + s_p[3 * DIM + c];

        if (ks == 0) {
            float s1 = pre, s2 = pre * pre;
            #pragma unroll
            for (int off = 16; off > 0; off >>= 1) {
                s1 += __shfl_xor_sync(0xffffffffu, s1, off);
                s2 += __shfl_xor_sync(0xffffffffu, s2, off);
            }
            if ((c & 31) == 0) {
                s_red[c >> 5] = s1;
                s_red[4 + (c >> 5)] = s2;
            }
        }
        __syncthreads();

        if (ks == 0) {
            float mu = (s_red[0] + s_red[1] + s_red[2] + s_red[3]) * (1.0f / 128.0f);
            float ex2 = (s_red[4] + s_red[5] + s_red[6] + s_red[7]) * (1.0f / 128.0f);
            float var = ex2 - mu * mu;
            float hn = (pre - mu) * rsqrtf(var + LN_EPS) * g_c + b_c;
            s_h[c] = fmaxf(hn, 0.0f);
        }
        __syncthreads();

        float op = 0.0f;
        {
            const float* hb = s_h + ks * 32;
            #pragma unroll
            for (int k = 0; k < 32; ++k) op += hb[k] * wv3[k];
        }
        s_p[ks * DIM + c] = op;
        __syncthreads();
        if (ks == 0) {
            float v = s_p[c] + s_p[DIM + c] + s_p[2 * DIM + c] + s_p[3 * DIM + c] + ar;
            out[r * DIM + c] = fmaxf(v, 0.0f);
        }
    }
}

// ---------------------------------------------------------------------------
extern "C" void kernel_launch(void* const* d_in, const int* in_sizes, int n_in,
                              void* d_out, int out_size)
{
    const float* agents = (const float*)d_in[0];
    const float* lanes  = (const float*)d_in[1];
    const float* Wq     = (const float*)d_in[2];
    const float* Wk     = (const float*)d_in[3];
    const float* Wv     = (const float*)d_in[4];
    const float* Wout1  = (const float*)d_in[5];
    const float* Wout2  = (const float*)d_in[6];
    const float* W1     = (const float*)d_in[7];
    const float* lng    = (const float*)d_in[8];
    const float* lnb    = (const float*)d_in[9];
    const float* W2     = (const float*)d_in[10];
    (void)in_sizes; (void)n_in; (void)out_size;

    cudaFuncSetAttribute(fused_kernel,
                         cudaFuncAttributeMaxDynamicSharedMemorySize, FUSED_SMEM);

    fused_kernel<<<NCTA, NTHR, FUSED_SMEM>>>(agents, lanes, Wq, Wk, Wv,
                                             Wout1, Wout2, W1, lng, lnb, W2,
                                             (float*)d_out);
}

// round 11
// speedup vs baseline: 1.0529x; 1.0529x over previous
#include <cuda_runtime.h>
#include <cuda_bf16.h>
#include <math.h>
#include <stdint.h>

// Problem constants (fixed by setup_inputs)
#define NB      8
#define NA      16
#define NL      80
#define DIM     128
#define NH      6
#define HD      768
#define N_AGT   128
#define N_NODE  768
#define SPS     96
#define NQKV    2304          // 3 * HD
#define LN_EPS  1e-5f

#define NCTA    128
#define NTHR    512

// Scratch (device globals: no allocations allowed)
__device__ float g_QKV[N_NODE * NQKV];        // cols: [Q | K | V(relu)]
__device__ float g_part[NH * N_AGT * DIM];    // per-head partials of attO@Wout1
__device__ unsigned g_gen = 0;                 // grid barrier generation
__device__ unsigned g_cnt = 0;                 // grid barrier counter

// ---------------------------------------------------------------------------
// Helpers
// ---------------------------------------------------------------------------
__device__ __forceinline__ uint32_t smem_u32(const void* p) {
    uint32_t a;
    asm("{ .reg .u64 t; cvta.to.shared.u64 t, %1; cvt.u32.u64 %0, t; }"
        : "=r"(a) : "l"(p));
    return a;
}
__device__ __forceinline__ void ldsm4(uint32_t* r, uint32_t a) {
    asm volatile("ldmatrix.sync.aligned.m8n8.x4.shared.b16 {%0,%1,%2,%3}, [%4];"
                 : "=r"(r[0]), "=r"(r[1]), "=r"(r[2]), "=r"(r[3]) : "r"(a));
}
__device__ __forceinline__ void ldsm2t(uint32_t* r, uint32_t a) {
    asm volatile("ldmatrix.sync.aligned.m8n8.x2.trans.shared.b16 {%0,%1}, [%2];"
                 : "=r"(r[0]), "=r"(r[1]) : "r"(a));
}
__device__ __forceinline__ void mma_bf16(float* d, const uint32_t* a,
                                         const uint32_t* b) {
    asm volatile(
        "mma.sync.aligned.m16n8k16.row.col.f32.bf16.bf16.f32 "
        "{%0,%1,%2,%3}, {%4,%5,%6,%7}, {%8,%9}, {%0,%1,%2,%3};"
        : "+f"(d[0]), "+f"(d[1]), "+f"(d[2]), "+f"(d[3])
        : "r"(a[0]), "r"(a[1]), "r"(a[2]), "r"(a[3]), "r"(b[0]), "r"(b[1]));
}
__device__ __forceinline__ void split2(float x, float y,
                                       uint32_t& hi, uint32_t& lo) {
    __nv_bfloat16 hx = __float2bfloat16_rn(x);
    __nv_bfloat16 hy = __float2bfloat16_rn(y);
    __nv_bfloat16 lx = __float2bfloat16_rn(x - __bfloat162float(hx));
    __nv_bfloat16 ly = __float2bfloat16_rn(y - __bfloat162float(hy));
    __nv_bfloat162 h = __halves2bfloat162(hx, hy);
    __nv_bfloat162 l = __halves2bfloat162(lx, ly);
    hi = *(uint32_t*)&h;
    lo = *(uint32_t*)&l;
}

// Grid-wide barrier: counter + monotonic generation (safe across graph replays)
__device__ __forceinline__ void grid_barrier() {
    __threadfence();
    __syncthreads();
    if (threadIdx.x == 0) {
        volatile unsigned* vg = &g_gen;
        unsigned my = *vg;
        if (atomicAdd(&g_cnt, 1u) == NCTA - 1u) {
            g_cnt = 0u;
            __threadfence();
            *vg = my + 1u;
        } else {
            while (*vg == my) { }
        }
    }
    __syncthreads();
    __threadfence();
}

// ---------------------------------------------------------------------------
// Fused single kernel. Phase A: 78 one-per-CTA 128x128 QKV tiles ->
// barrier -> Phase B: attention (48 CTAs) -> barrier -> Phase C: tail.
// ---------------------------------------------------------------------------
#define ASTR   136                       // row stride (bf16) for A and B
#define TA     (128 * ASTR * 2)          // 34816 B per buffer
#define KP     132
#define SP     100
#define FUSED_SMEM (4 * TA)              // 139264 B (>= attn's 114688)

__global__ __launch_bounds__(NTHR)
void fused_kernel(const float* __restrict__ agents,
                  const float* __restrict__ lanes,
                  const float* __restrict__ Wq,
                  const float* __restrict__ Wk,
                  const float* __restrict__ Wv,
                  const float* __restrict__ Wout1,
                  const float* __restrict__ Wout2,
                  const float* __restrict__ W1,
                  const float* __restrict__ lng,
                  const float* __restrict__ lnb,
                  const float* __restrict__ W2,
                  float* __restrict__ out)
{
    extern __shared__ float sm[];
    const uint32_t sb = smem_u32(sm);
    const int tid = threadIdx.x, wid = tid >> 5, lane = tid & 31;
    const int cta = blockIdx.x;

    // ===================== Phase A: QKV bf16x3 MMA (CTAs 0..77) ==============
    if (cta < 78) {
        const int t = cta;
        char* Ahi = (char*)sm;
        char* Alo = (char*)sm + TA;
        char* Bhi = (char*)sm + 2 * TA;
        char* Blo = (char*)sm + 3 * TA;

        int row0, col0;
        if (t < 72) { row0 = (t % 6) * 128; col0 = 768 + (t / 6) * 128; }
        else        { row0 = 0;              col0 = (t - 72) * 128;     }
        const float* __restrict__ W;
        int jl0;
        if (col0 < HD)          { W = Wq; jl0 = col0; }
        else if (col0 < 2 * HD) { W = Wk; jl0 = col0 - HD; }
        else                    { W = Wv; jl0 = col0 - 2 * HD; }

        // Fill A (128 rows x 128 k) and B (128 k x 128 n), fp32->bf16 hi/lo
        #pragma unroll
        for (int i = 0; i < 8; ++i) {
            int lin = tid + i * NTHR;            // 0..4095 float4s
            int q4 = (lin & 31) * 4;
            int rk = lin >> 5;
            uint32_t h0, l0, h1, l1;

            int grow = row0 + rk;
            const float* asrc = (grow < N_AGT) ? agents + grow * DIM
                                               : lanes + (grow - N_AGT) * DIM;
            float4 av = *(const float4*)(asrc + q4);
            split2(av.x, av.y, h0, l0);
            split2(av.z, av.w, h1, l1);
            *(uint2*)(Ahi + rk * (ASTR * 2) + q4 * 2) = make_uint2(h0, h1);
            *(uint2*)(Alo + rk * (ASTR * 2) + q4 * 2) = make_uint2(l0, l1);

            float4 bv = *(const float4*)(W + rk * HD + jl0 + q4);
            split2(bv.x, bv.y, h0, l0);
            split2(bv.z, bv.w, h1, l1);
            *(uint2*)(Bhi + rk * (ASTR * 2) + q4 * 2) = make_uint2(h0, h1);
            *(uint2*)(Blo + rk * (ASTR * 2) + q4 * 2) = make_uint2(l0, l1);
        }
        __syncthreads();

        // 16 warps: 4m x 4n, warp tile 32x32
        const int wm = wid >> 2, wn = wid & 3;
        const int m0 = wm * 32, n0 = wn * 32;
        float acc[2][4][4] = {};

        const uint32_t a_off = (uint32_t)((m0 + (lane & 15)) * ASTR +
                                          (lane >> 4) * 8) * 2;
        const uint32_t b_off = (uint32_t)((lane & 15) * ASTR + n0) * 2;
        const uint32_t sA_hi = sb + a_off;
        const uint32_t sA_lo = sb + TA + a_off;
        const uint32_t sB_hi = sb + 2 * TA + b_off;
        const uint32_t sB_lo = sb + 3 * TA + b_off;

        #pragma unroll 2
        for (int ks = 0; ks < 8; ++ks) {
            const uint32_t kbA = (uint32_t)(ks * 32);            // k along A cols
            const uint32_t kbB = (uint32_t)(ks * 16 * ASTR * 2); // k along B rows
            uint32_t ah[2][4], al[2][4], bh[4][2], bl[4][2];
            #pragma unroll
            for (int mt = 0; mt < 2; ++mt) {
                uint32_t moff = kbA + (uint32_t)(mt * 16 * ASTR * 2);
                ldsm4(ah[mt], sA_hi + moff);
                ldsm4(al[mt], sA_lo + moff);
            }
            #pragma unroll
            for (int nt = 0; nt < 4; ++nt) {
                ldsm2t(bh[nt], sB_hi + kbB + nt * 16);
                ldsm2t(bl[nt], sB_lo + kbB + nt * 16);
            }
            #pragma unroll
            for (int mt = 0; mt < 2; ++mt)
                #pragma unroll
                for (int nt = 0; nt < 4; ++nt) {
                    mma_bf16(acc[mt][nt], ah[mt], bh[nt]);
                    mma_bf16(acc[mt][nt], ah[mt], bl[nt]);
                    mma_bf16(acc[mt][nt], al[mt], bh[nt]);
                }
        }

        const bool dorelu = (col0 >= 2 * HD);
        const int rbase = row0 + m0 + (lane >> 2);
        const int cbase = col0 + n0 + (lane & 3) * 2;
        #pragma unroll
        for (int mt = 0; mt < 2; ++mt) {
            #pragma unroll
            for (int nt = 0; nt < 4; ++nt) {
                float2 v01 = make_float2(acc[mt][nt][0], acc[mt][nt][1]);
                float2 v23 = make_float2(acc[mt][nt][2], acc[mt][nt][3]);
                if (dorelu) {
                    v01.x = fmaxf(v01.x, 0.f); v01.y = fmaxf(v01.y, 0.f);
                    v23.x = fmaxf(v23.x, 0.f); v23.y = fmaxf(v23.y, 0.f);
                }
                int r = rbase + mt * 16;
                int c = cbase + nt * 8;
                *(float2*)(g_QKV + (size_t)r * NQKV + c) = v01;
                *(float2*)(g_QKV + (size_t)(r + 8) * NQKV + c) = v23;
            }
        }
    }

    grid_barrier();

    // ===================== Phase B: attention (CTAs 0..47) =====================
    if (cta < NB * NH) {
        const int b = cta / NH;
        const int h = cta % NH;
        float* Kt = sm;                      // [96][KP]
        float* Vt = Kt + SPS * KP;           // [96][128]
        float* Qs = Vt + SPS * DIM;          // [16][KP] -> later Ot[16][128]
        float* S  = Qs + NA * KP;            // [16][SP]

        #pragma unroll
        for (int i = 0; i < 6; ++i) {
            int lin = tid + i * NTHR;        // 0..3071
            int j = lin >> 5, f = lin & 31;
            int g = (j < NA) ? (b * NA + j) : (N_AGT + b * NL + (j - NA));
            const float* base = g_QKV + (size_t)g * NQKV + h * DIM + f * 4;
            *(float4*)(Kt + j * KP + f * 4) = *(const float4*)(base + HD);
            *(float4*)(Vt + j * DIM + f * 4) = *(const float4*)(base + 2 * HD);
        }
        {
            int r = tid >> 5, f = tid & 31;  // 512 = 16 rows x 32 float4
            *(float4*)(Qs + r * KP + f * 4) =
                *(const float4*)(g_QKV + (size_t)(b * NA + r) * NQKV + h * DIM + f * 4);
        }
        __syncthreads();

        // Scores: 384 threads, thread = (4 rows, 1 col)
        const float scale = 0.08838834764831845f;
        if (tid < 384) {
            const int ti = tid / SPS;        // 0..3
            const int tj = tid % SPS;        // col j
            const int ib = ti * 4;
            float acc[4] = {};
            #pragma unroll 4
            for (int k = 0; k < DIM; k += 4) {
                float4 kv = *(const float4*)(Kt + tj * KP + k);
                #pragma unroll
                for (int r = 0; r < 4; ++r) {
                    float4 q = *(const float4*)(Qs + (ib + r) * KP + k);
                    acc[r] += q.x * kv.x + q.y * kv.y + q.z * kv.z + q.w * kv.w;
                }
            }
            #pragma unroll
            for (int r = 0; r < 4; ++r)
                S[(ib + r) * SP + tj] = acc[r] * scale;
        }
        __syncthreads();

        // Softmax: warp w -> row w
        {
            const int i = wid;
            float v0 = S[i * SP + lane];
            float v1 = S[i * SP + lane + 32];
            float v2 = S[i * SP + lane + 64];
            float m = fmaxf(fmaxf(v0, v1), v2);
            #pragma unroll
            for (int off = 16; off > 0; off >>= 1)
                m = fmaxf(m, __shfl_xor_sync(0xffffffffu, m, off));
            float e0 = __expf(v0 - m), e1 = __expf(v1 - m), e2 = __expf(v2 - m);
            float s = e0 + e1 + e2;
            #pragma unroll
            for (int off = 16; off > 0; off >>= 1)
                s += __shfl_xor_sync(0xffffffffu, s, off);
            float rinv = 1.0f / s;
            S[i * SP + lane]      = e0 * rinv;
            S[i * SP + lane + 32] = e1 * rinv;
            S[i * SP + lane + 64] = e2 * rinv;
        }
        __syncthreads();

        // PV: warp = row, lane = 4 cols
        float* Ot = Qs;
        {
            const int i = wid;
            const int d = lane * 4;
            float4 a0 = make_float4(0.f, 0.f, 0.f, 0.f);
            #pragma unroll 4
            for (int k = 0; k < SPS; ++k) {
                float p = S[i * SP + k];
                float4 v = *(const float4*)(Vt + k * DIM + d);
                a0.x += p * v.x; a0.y += p * v.y; a0.z += p * v.z; a0.w += p * v.w;
            }
            *(float4*)(Ot + i * DIM + d) = a0;
        }
        __syncthreads();

        // Partial P1 = Ot(16x128) @ Wout1[h*128 .. +128, :]  (4-way k split)
        {
            const int c = tid & 127;
            const int ks = tid >> 7;         // 0..3
            float acc[NA] = {};
            const float* Wb = Wout1 + (size_t)(h * DIM + ks * 32) * DIM + c;
            #pragma unroll 8
            for (int kk = 0; kk < 32; ++kk) {
                float w = Wb[kk * DIM];
                const float* o = Ot + ks * 32 + kk;
                #pragma unroll
                for (int r = 0; r < NA; ++r)
                    acc[r] += o[r * DIM] * w;
            }
            float* red = Kt;                 // [3][16][128] fits in Kt region
            if (ks > 0) {
                #pragma unroll
                for (int r = 0; r < NA; ++r)
                    red[(ks - 1) * (NA * DIM) + r * DIM + c] = acc[r];
            }
            __syncthreads();
            if (ks == 0) {
                float* dst = g_part + (size_t)h * N_AGT * DIM +
                             (size_t)(b * NA) * DIM + c;
                #pragma unroll
                for (int r = 0; r < NA; ++r)
                    dst[r * DIM] = acc[r] + red[r * DIM + c]
                                          + red[NA * DIM + r * DIM + c]
                                          + red[2 * NA * DIM + r * DIM + c];
            }
        }
    }

    grid_barrier();

    // ===================== Phase C: tail (1 row per CTA) =====================
    {
        const int r = cta;
        const int c = tid & 127;
        const int ks = tid >> 7;             // 0..3

        float* s_ar = sm;                    // [128]
        float* s_t1 = sm + 128;              // [128]
        float* s_h  = sm + 256;              // [128]
        float* s_p  = sm + 384;              // [4][128]
        float* s_red = sm + 896;             // [8]

        float wv2[32], wv1[32];
        {
            const float* w2b = Wout2 + (size_t)(ks * 32) * DIM + c;
            const float* w1b = W1 + (size_t)(ks * 32) * DIM + c;
            #pragma unroll
            for (int k = 0; k < 32; ++k) {
                wv2[k] = w2b[k * DIM];
                wv1[k] = w1b[k * DIM];
            }
        }
        float tp = 0.0f;
        if (ks < 3) {
            const float* gp = g_part + (size_t)(2 * ks) * N_AGT * DIM +
                              (size_t)r * DIM + c;
            tp = gp[0] + gp[N_AGT * DIM];
        }
        const float ar = agents[r * DIM + c];
        const float g_c = lng[c], b_c = lnb[c];

        s_p[ks * DIM + c] = tp;
        __syncthreads();
        if (ks == 0) {
            s_t1[c] = fmaxf(s_p[c] + s_p[DIM + c] + s_p[2 * DIM + c], 0.0f);
            s_ar[c] = ar;
        }
        __syncthreads();

        float pp = 0.0f;
        {
            const float* t1b = s_t1 + ks * 32;
            const float* arb = s_ar + ks * 32;
            #pragma unroll
            for (int k = 0; k < 32; ++k)
                pp += t1b[k] * wv2[k] + arb[k] * wv1[k];
        }
        s_p[ks * DIM + c] = pp;

        float wv3[32];
        {
            const float* w3b = W2 + (size_t)(ks * 32) * DIM + c;
            #pragma unroll
            for (int k = 0; k < 32; ++k) wv3[k] = w3b[k * DIM];
        }
        __syncthreads();

        const float pre = s_p[c] + s_p[DIM + c] + s_p[2 * DIM + c] + s_p[3 * DIM + c];

        if (ks == 0) {
            float s1 = pre, s2 = pre * pre;
            #pragma unroll
            for (int off = 16; off > 0; off >>= 1) {
                s1 += __shfl_xor_sync(0xffffffffu, s1, off);
                s2 += __shfl_xor_sync(0xffffffffu, s2, off);
            }
            if ((c & 31) == 0) {
                s_red[c >> 5] = s1;
                s_red[4 + (c >> 5)] = s2;
            }
        }
        __syncthreads();

        if (ks == 0) {
            float mu = (s_red[0] + s_red[1] + s_red[2] + s_red[3]) * (1.0f / 128.0f);
            float ex2 = (s_red[4] + s_red[5] + s_red[6] + s_red[7]) * (1.0f / 128.0f);
            float var = ex2 - mu * mu;
            float hn = (pre - mu) * rsqrtf(var + LN_EPS) * g_c + b_c;
            s_h[c] = fmaxf(hn, 0.0f);
        }
        __syncthreads();

        float op = 0.0f;
        {
            const float* hb = s_h + ks * 32;
            #pragma unroll
            for (int k = 0; k < 32; ++k) op += hb[k] * wv3[k];
        }
        s_p[ks * DIM + c] = op;
        __syncthreads();
        if (ks == 0) {
            float v = s_p[c] + s_p[DIM + c] + s_p[2 * DIM + c] + s_p[3 * DIM + c] + ar;
            out[r * DIM + c] = fmaxf(v, 0.0f);
        }
    }
}

// ---------------------------------------------------------------------------
extern "C" void kernel_launch(void* const* d_in, const int* in_sizes, int n_in,
                              void* d_out, int out_size)
{
    const float* agents = (const float*)d_in[0];
    const float* lanes  = (const float*)d_in[1];
    const float* Wq     = (const float*)d_in[2];
    const float* Wk     = (const float*)d_in[3];
    const float* Wv     = (const float*)d_in[4];
    const float* Wout1  = (const float*)d_in[5];
    const float* Wout2  = (const float*)d_in[6];
    const float* W1     = (const float*)d_in[7];
    const float* lng    = (const float*)d_in[8];
    const float* lnb    = (const float*)d_in[9];
    const float* W2     = (const float*)d_in[10];
    (void)in_sizes; (void)n_in; (void)out_size;

    cudaFuncSetAttribute(fused_kernel,
                         cudaFuncAttributeMaxDynamicSharedMemorySize, FUSED_SMEM);

    fused_kernel<<<NCTA, NTHR, FUSED_SMEM>>>(agents, lanes, Wq, Wk, Wv,
                                             Wout1, Wout2, W1, lng, lnb, W2,
                                             (float*)d_out);
}

// round 12
// speedup vs baseline: 1.1523x; 1.0945x over previous
#include <cuda_runtime.h>
#include <cuda_bf16.h>
#include <math.h>
#include <stdint.h>

// Problem constants (fixed by setup_inputs)
#define NB      8
#define NA      16
#define NL      80
#define DIM     128
#define NH      6
#define HD      768
#define N_AGT   128
#define N_NODE  768
#define SPS     96
#define NQKV    2304          // 3 * HD
#define LN_EPS  1e-5f

// Scratch (device globals: no allocations allowed)
__device__ float g_QKV[N_NODE * NQKV];        // cols: [Q | K | V(relu)]
__device__ float g_part[NH * N_AGT * DIM];    // per-head partials of attO@Wout1

// ---------------------------------------------------------------------------
// Helpers (mma.sync / ldmatrix — valid on compute_103)
// ---------------------------------------------------------------------------
__device__ __forceinline__ uint32_t smem_u32(const void* p) {
    uint32_t a;
    asm("{ .reg .u64 t; cvta.to.shared.u64 t, %1; cvt.u32.u64 %0, t; }"
        : "=r"(a) : "l"(p));
    return a;
}
__device__ __forceinline__ void ldsm4(uint32_t* r, uint32_t a) {
    asm volatile("ldmatrix.sync.aligned.m8n8.x4.shared.b16 {%0,%1,%2,%3}, [%4];"
                 : "=r"(r[0]), "=r"(r[1]), "=r"(r[2]), "=r"(r[3]) : "r"(a));
}
__device__ __forceinline__ void ldsm2t(uint32_t* r, uint32_t a) {
    asm volatile("ldmatrix.sync.aligned.m8n8.x2.trans.shared.b16 {%0,%1}, [%2];"
                 : "=r"(r[0]), "=r"(r[1]) : "r"(a));
}
__device__ __forceinline__ void mma_bf16(float* d, const uint32_t* a,
                                         const uint32_t* b) {
    asm volatile(
        "mma.sync.aligned.m16n8k16.row.col.f32.bf16.bf16.f32 "
        "{%0,%1,%2,%3}, {%4,%5,%6,%7}, {%8,%9}, {%0,%1,%2,%3};"
        : "+f"(d[0]), "+f"(d[1]), "+f"(d[2]), "+f"(d[3])
        : "r"(a[0]), "r"(a[1]), "r"(a[2]), "r"(a[3]), "r"(b[0]), "r"(b[1]));
}
// Fast bf16 hi/lo split of two floats. hi = truncated top-16 bits (packed with
// one PRMT); lo = exact residual rounded to bf16 (one packed CVT). a = hi + lo
// to within 2^-16 relative — same compensated-product accuracy as rn split.
__device__ __forceinline__ void split2(float x, float y,
                                       uint32_t& hi, uint32_t& lo) {
    uint32_t xb = __float_as_uint(x), yb = __float_as_uint(y);
    uint32_t h;
    asm("prmt.b32 %0, %1, %2, 0x7632;" : "=r"(h) : "r"(xb), "r"(yb));
    float xh = __uint_as_float(xb & 0xFFFF0000u);
    float yh = __uint_as_float(yb & 0xFFFF0000u);
    uint32_t l;
    asm("cvt.rn.bf16x2.f32 %0, %1, %2;" : "=r"(l) : "f"(y - yh), "f"(x - xh));
    hi = h;
    lo = l;
}

// ---------------------------------------------------------------------------
// Kernel 1: QKV bf16x3 MMA. 78 CTAs x 512 threads, one 128x128 tile each.
// (verified as fused phase A in rounds 10-11)
// ---------------------------------------------------------------------------
#define ASTR   136                       // row stride (bf16) for A and B
#define TA     (128 * ASTR * 2)          // 34816 B per buffer
#define MMA_SMEM (4 * TA)                // 139264 B

__global__ __launch_bounds__(512)
void qkv_mma(const float* __restrict__ agents,
             const float* __restrict__ lanes,
             const float* __restrict__ Wq,
             const float* __restrict__ Wk,
             const float* __restrict__ Wv)
{
    extern __shared__ float sm[];
    const uint32_t sb = smem_u32(sm);
    const int tid = threadIdx.x, wid = tid >> 5, lane = tid & 31;
    const int t = blockIdx.x;

    char* Ahi = (char*)sm;
    char* Alo = (char*)sm + TA;
    char* Bhi = (char*)sm + 2 * TA;
    char* Blo = (char*)sm + 3 * TA;

    int row0, col0;
    if (t < 72) { row0 = (t % 6) * 128; col0 = 768 + (t / 6) * 128; }
    else        { row0 = 0;              col0 = (t - 72) * 128;     }
    const float* __restrict__ W;
    int jl0;
    if (col0 < HD)          { W = Wq; jl0 = col0; }
    else if (col0 < 2 * HD) { W = Wk; jl0 = col0 - HD; }
    else                    { W = Wv; jl0 = col0 - 2 * HD; }

    // Fill A (128 rows x 128 k) and B (128 k x 128 n), fp32->bf16 hi/lo
    #pragma unroll
    for (int i = 0; i < 8; ++i) {
        int lin = tid + i * 512;             // 0..4095 float4s
        int q4 = (lin & 31) * 4;
        int rk = lin >> 5;
        uint32_t h0, l0, h1, l1;

        int grow = row0 + rk;
        const float* asrc = (grow < N_AGT) ? agents + grow * DIM
                                           : lanes + (grow - N_AGT) * DIM;
        float4 av = *(const float4*)(asrc + q4);
        split2(av.x, av.y, h0, l0);
        split2(av.z, av.w, h1, l1);
        *(uint2*)(Ahi + rk * (ASTR * 2) + q4 * 2) = make_uint2(h0, h1);
        *(uint2*)(Alo + rk * (ASTR * 2) + q4 * 2) = make_uint2(l0, l1);

        float4 bv = *(const float4*)(W + rk * HD + jl0 + q4);
        split2(bv.x, bv.y, h0, l0);
        split2(bv.z, bv.w, h1, l1);
        *(uint2*)(Bhi + rk * (ASTR * 2) + q4 * 2) = make_uint2(h0, h1);
        *(uint2*)(Blo + rk * (ASTR * 2) + q4 * 2) = make_uint2(l0, l1);
    }
    __syncthreads();

    // 16 warps: 4m x 4n, warp tile 32x32
    const int wm = wid >> 2, wn = wid & 3;
    const int m0 = wm * 32, n0 = wn * 32;
    float acc[2][4][4] = {};

    const uint32_t a_off = (uint32_t)((m0 + (lane & 15)) * ASTR +
                                      (lane >> 4) * 8) * 2;
    const uint32_t b_off = (uint32_t)((lane & 15) * ASTR + n0) * 2;
    const uint32_t sA_hi = sb + a_off;
    const uint32_t sA_lo = sb + TA + a_off;
    const uint32_t sB_hi = sb + 2 * TA + b_off;
    const uint32_t sB_lo = sb + 3 * TA + b_off;

    #pragma unroll 2
    for (int ks = 0; ks < 8; ++ks) {
        const uint32_t kbA = (uint32_t)(ks * 32);            // k along A cols
        const uint32_t kbB = (uint32_t)(ks * 16 * ASTR * 2); // k along B rows
        uint32_t ah[2][4], al[2][4], bh[4][2], bl[4][2];
        #pragma unroll
        for (int mt = 0; mt < 2; ++mt) {
            uint32_t moff = kbA + (uint32_t)(mt * 16 * ASTR * 2);
            ldsm4(ah[mt], sA_hi + moff);
            ldsm4(al[mt], sA_lo + moff);
        }
        #pragma unroll
        for (int nt = 0; nt < 4; ++nt) {
            ldsm2t(bh[nt], sB_hi + kbB + nt * 16);
            ldsm2t(bl[nt], sB_lo + kbB + nt * 16);
        }
        #pragma unroll
        for (int mt = 0; mt < 2; ++mt)
            #pragma unroll
            for (int nt = 0; nt < 4; ++nt) {
                mma_bf16(acc[mt][nt], ah[mt], bh[nt]);
                mma_bf16(acc[mt][nt], ah[mt], bl[nt]);
                mma_bf16(acc[mt][nt], al[mt], bh[nt]);
            }
    }

    const bool dorelu = (col0 >= 2 * HD);
    const int rbase = row0 + m0 + (lane >> 2);
    const int cbase = col0 + n0 + (lane & 3) * 2;
    #pragma unroll
    for (int mt = 0; mt < 2; ++mt) {
        #pragma unroll
        for (int nt = 0; nt < 4; ++nt) {
            float2 v01 = make_float2(acc[mt][nt][0], acc[mt][nt][1]);
            float2 v23 = make_float2(acc[mt][nt][2], acc[mt][nt][3]);
            if (dorelu) {
                v01.x = fmaxf(v01.x, 0.f); v01.y = fmaxf(v01.y, 0.f);
                v23.x = fmaxf(v23.x, 0.f); v23.y = fmaxf(v23.y, 0.f);
            }
            int r = rbase + mt * 16;
            int c = cbase + nt * 8;
            *(float2*)(g_QKV + (size_t)r * NQKV + c) = v01;
            *(float2*)(g_QKV + (size_t)(r + 8) * NQKV + c) = v23;
        }
    }
}

// ---------------------------------------------------------------------------
// Kernel 2: attention + per-head Wout1 partial. 48 CTAs x 512 threads.
// (verified as fused phase B in rounds 10-11)
// ---------------------------------------------------------------------------
#define KP 132
#define SP 100
#define ATTN_SMEM ((SPS*KP + SPS*DIM + NA*KP + NA*SP) * 4)

__global__ __launch_bounds__(512)
void attn_kernel(const float* __restrict__ Wout1)
{
    const int cta = blockIdx.x;
    const int b = cta / NH;
    const int h = cta % NH;
    const int tid = threadIdx.x, wid = tid >> 5, lane = tid & 31;
    extern __shared__ float sm[];
    float* Kt = sm;                      // [96][KP]
    float* Vt = Kt + SPS * KP;           // [96][128]
    float* Qs = Vt + SPS * DIM;          // [16][KP] -> later Ot[16][128]
    float* S  = Qs + NA * KP;            // [16][SP]

    #pragma unroll
    for (int i = 0; i < 6; ++i) {
        int lin = tid + i * 512;         // 0..3071
        int j = lin >> 5, f = lin & 31;
        int g = (j < NA) ? (b * NA + j) : (N_AGT + b * NL + (j - NA));
        const float* base = g_QKV + (size_t)g * NQKV + h * DIM + f * 4;
        *(float4*)(Kt + j * KP + f * 4) = *(const float4*)(base + HD);
        *(float4*)(Vt + j * DIM + f * 4) = *(const float4*)(base + 2 * HD);
    }
    {
        int r = tid >> 5, f = tid & 31;  // 512 = 16 rows x 32 float4
        *(float4*)(Qs + r * KP + f * 4) =
            *(const float4*)(g_QKV + (size_t)(b * NA + r) * NQKV + h * DIM + f * 4);
    }
    __syncthreads();

    // Scores: 384 threads, thread = (4 rows, 1 col)
    const float scale = 0.08838834764831845f;
    if (tid < 384) {
        const int ti = tid / SPS;        // 0..3
        const int tj = tid % SPS;        // col j
        const int ib = ti * 4;
        float acc[4] = {};
        #pragma unroll 4
        for (int k = 0; k < DIM; k += 4) {
            float4 kv = *(const float4*)(Kt + tj * KP + k);
            #pragma unroll
            for (int r = 0; r < 4; ++r) {
                float4 q = *(const float4*)(Qs + (ib + r) * KP + k);
                acc[r] += q.x * kv.x + q.y * kv.y + q.z * kv.z + q.w * kv.w;
            }
        }
        #pragma unroll
        for (int r = 0; r < 4; ++r)
            S[(ib + r) * SP + tj] = acc[r] * scale;
    }
    __syncthreads();

    // Softmax: warp w -> row w
    {
        const int i = wid;
        float v0 = S[i * SP + lane];
        float v1 = S[i * SP + lane + 32];
        float v2 = S[i * SP + lane + 64];
        float m = fmaxf(fmaxf(v0, v1), v2);
        #pragma unroll
        for (int off = 16; off > 0; off >>= 1)
            m = fmaxf(m, __shfl_xor_sync(0xffffffffu, m, off));
        float e0 = __expf(v0 - m), e1 = __expf(v1 - m), e2 = __expf(v2 - m);
        float s = e0 + e1 + e2;
        #pragma unroll
        for (int off = 16; off > 0; off >>= 1)
            s += __shfl_xor_sync(0xffffffffu, s, off);
        float rinv = 1.0f / s;
        S[i * SP + lane]      = e0 * rinv;
        S[i * SP + lane + 32] = e1 * rinv;
        S[i * SP + lane + 64] = e2 * rinv;
    }
    __syncthreads();

    // PV: warp = row, lane = 4 cols
    float* Ot = Qs;
    {
        const int i = wid;
        const int d = lane * 4;
        float4 a0 = make_float4(0.f, 0.f, 0.f, 0.f);
        #pragma unroll 4
        for (int k = 0; k < SPS; ++k) {
            float p = S[i * SP + k];
            float4 v = *(const float4*)(Vt + k * DIM + d);
            a0.x += p * v.x; a0.y += p * v.y; a0.z += p * v.z; a0.w += p * v.w;
        }
        *(float4*)(Ot + i * DIM + d) = a0;
    }
    __syncthreads();

    // Partial P1 = Ot(16x128) @ Wout1[h*128 .. +128, :]  (4-way k split)
    {
        const int c = tid & 127;
        const int ks = tid >> 7;         // 0..3
        float acc[NA] = {};
        const float* Wb = Wout1 + (size_t)(h * DIM + ks * 32) * DIM + c;
        #pragma unroll 8
        for (int kk = 0; kk < 32; ++kk) {
            float w = Wb[kk * DIM];
            const float* o = Ot + ks * 32 + kk;
            #pragma unroll
            for (int r = 0; r < NA; ++r)
                acc[r] += o[r * DIM] * w;
        }
        float* red = Kt;                 // [3][16][128] fits in Kt region
        if (ks > 0) {
            #pragma unroll
            for (int r = 0; r < NA; ++r)
                red[(ks - 1) * (NA * DIM) + r * DIM + c] = acc[r];
        }
        __syncthreads();
        if (ks == 0) {
            float* dst = g_part + (size_t)h * N_AGT * DIM +
                         (size_t)(b * NA) * DIM + c;
            #pragma unroll
            for (int r = 0; r < NA; ++r)
                dst[r * DIM] = acc[r] + red[r * DIM + c]
                                      + red[NA * DIM + r * DIM + c]
                                      + red[2 * NA * DIM + r * DIM + c];
        }
    }
}

// ---------------------------------------------------------------------------
// Kernel 3: fused tail — 1 agent row per block, 512 threads, prefetched loads,
// warp-shuffle LayerNorm. (verified rounds 7-11)
// ---------------------------------------------------------------------------
__global__ __launch_bounds__(512)
void tail_kernel(const float* __restrict__ agents,
                 const float* __restrict__ Wout2,
                 const float* __restrict__ W1,
                 const float* __restrict__ lng,
                 const float* __restrict__ lnb,
                 const float* __restrict__ W2,
                 float* __restrict__ out)
{
    const int r = blockIdx.x;
    const int tid = threadIdx.x;
    const int c = tid & 127;
    const int ks = tid >> 7;              // 0..3

    __shared__ float s_ar[DIM];
    __shared__ float s_t1[DIM];
    __shared__ float s_h[DIM];
    __shared__ float s_p[4][DIM];
    __shared__ float s_red[8];

    float wv2[32], wv1[32];
    {
        const float* w2b = Wout2 + (size_t)(ks * 32) * DIM + c;
        const float* w1b = W1 + (size_t)(ks * 32) * DIM + c;
        #pragma unroll
        for (int k = 0; k < 32; ++k) {
            wv2[k] = w2b[k * DIM];
            wv1[k] = w1b[k * DIM];
        }
    }
    float tp = 0.0f;
    if (ks < 3) {
        const float* gp = g_part + (size_t)(2 * ks) * N_AGT * DIM + (size_t)r * DIM + c;
        tp = gp[0] + gp[N_AGT * DIM];
    }
    const float ar = agents[r * DIM + c];
    const float g_c = lng[c], b_c = lnb[c];

    s_p[ks][c] = tp;
    __syncthreads();
    if (ks == 0) {
        s_t1[c] = fmaxf(s_p[0][c] + s_p[1][c] + s_p[2][c], 0.0f);
        s_ar[c] = ar;
    }
    __syncthreads();

    float pp = 0.0f;
    {
        const float* t1b = s_t1 + ks * 32;
        const float* arb = s_ar + ks * 32;
        #pragma unroll
        for (int k = 0; k < 32; ++k)
            pp += t1b[k] * wv2[k] + arb[k] * wv1[k];
    }
    s_p[ks][c] = pp;

    float wv3[32];
    {
        const float* w3b = W2 + (size_t)(ks * 32) * DIM + c;
        #pragma unroll
        for (int k = 0; k < 32; ++k) wv3[k] = w3b[k * DIM];
    }
    __syncthreads();

    const float pre = s_p[0][c] + s_p[1][c] + s_p[2][c] + s_p[3][c];

    if (ks == 0) {
        float s1 = pre, s2 = pre * pre;
        #pragma unroll
        for (int off = 16; off > 0; off >>= 1) {
            s1 += __shfl_xor_sync(0xffffffffu, s1, off);
            s2 += __shfl_xor_sync(0xffffffffu, s2, off);
        }
        if ((c & 31) == 0) {
            s_red[c >> 5] = s1;
            s_red[4 + (c >> 5)] = s2;
        }
    }
    __syncthreads();

    if (ks == 0) {
        float mu = (s_red[0] + s_red[1] + s_red[2] + s_red[3]) * (1.0f / 128.0f);
        float ex2 = (s_red[4] + s_red[5] + s_red[6] + s_red[7]) * (1.0f / 128.0f);
        float var = ex2 - mu * mu;
        float hn = (pre - mu) * rsqrtf(var + LN_EPS) * g_c + b_c;
        s_h[c] = fmaxf(hn, 0.0f);
    }
    __syncthreads();

    float op = 0.0f;
    {
        const float* hb = s_h + ks * 32;
        #pragma unroll
        for (int k = 0; k < 32; ++k) op += hb[k] * wv3[k];
    }
    s_p[ks][c] = op;
    __syncthreads();
    if (ks == 0) {
        float v = s_p[0][c] + s_p[1][c] + s_p[2][c] + s_p[3][c] + ar;
        out[r * DIM + c] = fmaxf(v, 0.0f);
    }
}

// ---------------------------------------------------------------------------
extern "C" void kernel_launch(void* const* d_in, const int* in_sizes, int n_in,
                              void* d_out, int out_size)
{
    const float* agents = (const float*)d_in[0];
    const float* lanes  = (const float*)d_in[1];
    const float* Wq     = (const float*)d_in[2];
    const float* Wk     = (const float*)d_in[3];
    const float* Wv     = (const float*)d_in[4];
    const float* Wout1  = (const float*)d_in[5];
    const float* Wout2  = (const float*)d_in[6];
    const float* W1     = (const float*)d_in[7];
    const float* lng    = (const float*)d_in[8];
    const float* lnb    = (const float*)d_in[9];
    const float* W2     = (const float*)d_in[10];
    (void)in_sizes; (void)n_in; (void)out_size;

    cudaFuncSetAttribute(qkv_mma,
                         cudaFuncAttributeMaxDynamicSharedMemorySize, MMA_SMEM);
    cudaFuncSetAttribute(attn_kernel,
                         cudaFuncAttributeMaxDynamicSharedMemorySize, ATTN_SMEM);

    qkv_mma<<<78, 512, MMA_SMEM>>>(agents, lanes, Wq, Wk, Wv);
    attn_kernel<<<NB * NH, 512, ATTN_SMEM>>>(Wout1);
    tail_kernel<<<N_AGT, 512>>>(agents, Wout2, W1, lng, lnb, W2,
                                (float*)d_out);
}